// round 9
// baseline (speedup 1.0000x reference)
#include <cuda_runtime.h>
#include <cuda_bf16.h>
#include <math.h>
#include <stdint.h>

#define N_NODES 50000
#define E_EDGES 800000
#define DIN 256
#define DH 128
#define DOUT 64

// ---------------- scratch (static device globals; no allocation) ----------------
__device__ __nv_bfloat16 g_h[(size_t)N_NODES * DH];
__device__ __nv_bfloat16 g_a[(size_t)N_NODES * DH];
__device__ __nv_bfloat16 g_w0[DIN * DH];
__device__ __nv_bfloat16 g_w1[DH * DH];
__device__ __nv_bfloat16 g_w2[DH * DOUT];
__device__ float g_dinv[N_NODES];
__device__ int   g_deg[N_NODES];
__device__ int   g_offs[N_NODES + 1];
__device__ int   g_cursor[N_NODES];
__device__ int2  g_edge[E_EDGES];
__device__ unsigned long long g_state[64];

// ---------------- host-side stream/event singletons ----------------
struct HxStreams {
    cudaStream_t s2;
    cudaEvent_t ev0, ev1;
    HxStreams() {
        cudaStreamCreateWithFlags(&s2, cudaStreamNonBlocking);
        cudaEventCreateWithFlags(&ev0, cudaEventDisableTiming);
        cudaEventCreateWithFlags(&ev1, cudaEventDisableTiming);
    }
};
static HxStreams g_sx;

// ---------------- weight conversion ----------------
__global__ void k_cvt_w(const float* __restrict__ W0, const float* __restrict__ W1,
                        const float* __restrict__ W2) {
    int i = blockIdx.x * blockDim.x + threadIdx.x;
    const int c0 = DIN * DH / 8, c1 = DH * DH / 8, c2 = DH * DOUT / 8;
    const float* s; __nv_bfloat16* d; int off;
    if (i < c0) { s = W0; d = g_w0; off = i; }
    else if (i < c0 + c1) { s = W1; d = g_w1; off = i - c0; }
    else if (i < c0 + c1 + c2) { s = W2; d = g_w2; off = i - c0 - c1; }
    else return;
    const float4* p = (const float4*)(s + off * 8);
    float4 v0 = p[0], v1 = p[1];
    __nv_bfloat16 t[8];
    t[0] = __float2bfloat16(v0.x); t[1] = __float2bfloat16(v0.y);
    t[2] = __float2bfloat16(v0.z); t[3] = __float2bfloat16(v0.w);
    t[4] = __float2bfloat16(v1.x); t[5] = __float2bfloat16(v1.y);
    t[6] = __float2bfloat16(v1.z); t[7] = __float2bfloat16(v1.w);
    *(uint4*)(d + off * 8) = *(uint4*)t;
}

// ---------------- CSR construction ----------------
__global__ void k_count(const int* __restrict__ dst, int E) {
    int i4 = (blockIdx.x * blockDim.x + threadIdx.x) * 4;
    if (i4 + 3 < E) {
        int4 d = *(const int4*)(dst + i4);
        atomicAdd(&g_deg[d.x], 1);
        atomicAdd(&g_deg[d.y], 1);
        atomicAdd(&g_deg[d.z], 1);
        atomicAdd(&g_deg[d.w], 1);
    } else {
        for (int j = i4; j < E; j++) atomicAdd(&g_deg[dst[j]], 1);
    }
}

// 512 threads x 8 elems = 4096/block -> 13 blocks; single-round lookback.
__global__ void k_scan_all(int n, int nb) {
    __shared__ int wsum[16];
    __shared__ int s_base;
    const int t = threadIdx.x;
    const int lane = t & 31, w = t >> 5;
    const int base = blockIdx.x * 4096 + t * 8;

    int d[8];
    if (base + 7 < n) {
        int4 a = *(const int4*)(g_deg + base);
        int4 b = *(const int4*)(g_deg + base + 4);
        d[0] = a.x; d[1] = a.y; d[2] = a.z; d[3] = a.w;
        d[4] = b.x; d[5] = b.y; d[6] = b.z; d[7] = b.w;
    } else {
#pragma unroll
        for (int j = 0; j < 8; j++) d[j] = (base + j < n) ? g_deg[base + j] : 0;
    }
    if (base + 7 < n) {
        float4 f0 = make_float4(rsqrtf((float)d[0] + 1.f), rsqrtf((float)d[1] + 1.f),
                                rsqrtf((float)d[2] + 1.f), rsqrtf((float)d[3] + 1.f));
        float4 f1 = make_float4(rsqrtf((float)d[4] + 1.f), rsqrtf((float)d[5] + 1.f),
                                rsqrtf((float)d[6] + 1.f), rsqrtf((float)d[7] + 1.f));
        *(float4*)(g_dinv + base) = f0;
        *(float4*)(g_dinv + base + 4) = f1;
    } else {
#pragma unroll
        for (int j = 0; j < 8; j++)
            if (base + j < n) g_dinv[base + j] = rsqrtf((float)d[j] + 1.f);
    }

    int pre[8];
    int run = 0;
#pragma unroll
    for (int j = 0; j < 8; j++) { pre[j] = run; run += d[j]; }

    int ws = run;
#pragma unroll
    for (int off = 1; off < 32; off <<= 1) {
        int v = __shfl_up_sync(0xFFFFFFFFu, ws, off);
        if (lane >= off) ws += v;
    }
    if (lane == 31) wsum[w] = ws;
    __syncthreads();
    if (w == 0 && lane < 16) {
        int v = wsum[lane];
#pragma unroll
        for (int off = 1; off < 16; off <<= 1) {
            int u = __shfl_up_sync(0x0000FFFFu, v, off);
            if (lane >= off) v += u;
        }
        wsum[lane] = v;
    }
    __syncthreads();

    if (t == 0) {
        unsigned long long pkt = (((unsigned long long)(unsigned)wsum[15]) << 2) | 1ull;
        atomicExch(&g_state[blockIdx.x], pkt);
    }
    if (w == 0) {
        int sum = 0;
        volatile unsigned long long* st = (volatile unsigned long long*)g_state;
        for (int p0 = (int)blockIdx.x - 1; p0 >= 0; p0 -= 32) {
            int idx = p0 - lane;
            if (idx >= 0) {
                unsigned long long v;
                do { v = st[idx]; } while ((v & 3ull) == 0ull);
                sum += (int)(v >> 2);
            }
        }
#pragma unroll
        for (int off = 16; off > 0; off >>= 1)
            sum += __shfl_xor_sync(0xFFFFFFFFu, sum, off);
        if (lane == 0) s_base = sum;
    }
    __syncthreads();

    const int blk = s_base;
    int wbase = (w == 0) ? 0 : wsum[w - 1];
    int tbase = blk + wbase + ws - run;
    if (base + 7 < n) {
        int4 o0 = make_int4(tbase + pre[0], tbase + pre[1], tbase + pre[2], tbase + pre[3]);
        int4 o1 = make_int4(tbase + pre[4], tbase + pre[5], tbase + pre[6], tbase + pre[7]);
        *(int4*)(g_offs + base) = o0;   *(int4*)(g_offs + base + 4) = o1;
        *(int4*)(g_cursor + base) = o0; *(int4*)(g_cursor + base + 4) = o1;
    } else {
#pragma unroll
        for (int j = 0; j < 8; j++)
            if (base + j < n) { g_offs[base + j] = tbase + pre[j]; g_cursor[base + j] = tbase + pre[j]; }
    }
    if (blockIdx.x == (unsigned)(nb - 1) && t == 511) g_offs[n] = blk + wsum[15];
}

__global__ void k_fill(const int* __restrict__ src, const int* __restrict__ dst, int E) {
    int i4 = (blockIdx.x * blockDim.x + threadIdx.x) * 4;
    if (i4 + 3 < E) {
        int4 s = *(const int4*)(src + i4);
        int4 d = *(const int4*)(dst + i4);
        int p0 = atomicAdd(&g_cursor[d.x], 1);
        int p1 = atomicAdd(&g_cursor[d.y], 1);
        int p2 = atomicAdd(&g_cursor[d.z], 1);
        int p3 = atomicAdd(&g_cursor[d.w], 1);
        g_edge[p0] = make_int2(s.x, __float_as_int(g_dinv[s.x] * g_dinv[d.x]));
        g_edge[p1] = make_int2(s.y, __float_as_int(g_dinv[s.y] * g_dinv[d.y]));
        g_edge[p2] = make_int2(s.z, __float_as_int(g_dinv[s.z] * g_dinv[d.z]));
        g_edge[p3] = make_int2(s.w, __float_as_int(g_dinv[s.w] * g_dinv[d.w]));
    } else {
        for (int j = i4; j < E; j++) {
            int dd = dst[j], ss = src[j];
            int pos = atomicAdd(&g_cursor[dd], 1);
            g_edge[pos] = make_int2(ss, __float_as_int(g_dinv[ss] * g_dinv[dd]));
        }
    }
}

// ---------------- GEMM primitives ----------------
__device__ __forceinline__ uint32_t smem_u32(const void* p) {
    return (uint32_t)__cvta_generic_to_shared(p);
}
__device__ __forceinline__ void cp16(uint32_t dst, const void* src, int pred) {
    asm volatile("cp.async.cg.shared.global [%0], [%1], 16, %2;"
                 :: "r"(dst), "l"(src), "r"(pred ? 16 : 0));
}
__device__ __forceinline__ void cp_commit() {
    asm volatile("cp.async.commit_group;");
}
__device__ __forceinline__ void ldsm_x4(uint32_t r[4], uint32_t addr) {
    asm volatile("ldmatrix.sync.aligned.m8n8.x4.shared.b16 {%0,%1,%2,%3}, [%4];"
                 : "=r"(r[0]), "=r"(r[1]), "=r"(r[2]), "=r"(r[3]) : "r"(addr));
}
__device__ __forceinline__ void ldsm_x4_t(uint32_t r[4], uint32_t addr) {
    asm volatile("ldmatrix.sync.aligned.m8n8.x4.trans.shared.b16 {%0,%1,%2,%3}, [%4];"
                 : "=r"(r[0]), "=r"(r[1]), "=r"(r[2]), "=r"(r[3]) : "r"(addr));
}
__device__ __forceinline__ void mma_bf16(float c[4], const uint32_t a[4],
                                         uint32_t b0, uint32_t b1) {
    asm volatile(
        "mma.sync.aligned.m16n8k16.row.col.f32.bf16.bf16.f32 "
        "{%0,%1,%2,%3},{%4,%5,%6,%7},{%8,%9},{%0,%1,%2,%3};"
        : "+f"(c[0]), "+f"(c[1]), "+f"(c[2]), "+f"(c[3])
        : "r"(a[0]), "r"(a[1]), "r"(a[2]), "r"(a[3]), "r"(b0), "r"(b1));
}

// ============ bf16-input GEMM (layers 2,3): BM=128, 3-stage cp.async (R7-proven) ======
template <int K, int F>
__global__ void __launch_bounds__(256) k_gemm_bf16(const __nv_bfloat16* __restrict__ A,
                                                   const __nv_bfloat16* __restrict__ Wm,
                                                   __nv_bfloat16* __restrict__ C, int n) {
    constexpr int BM = 128, BK = 32, S = 3;
    constexpr int AST = 40;
    constexpr int WST = F + 8;
    constexpr int WNW = F / 2;
    constexpr int NT = WNW / 8;
    constexpr int KT = K / BK;
    constexpr int WCH = F / 8;
    constexpr int ACH = 2;
    constexpr int WQN = (BK * WCH + 255) / 256;

    __shared__ __align__(16) __nv_bfloat16 As[S][BM * AST];
    __shared__ __align__(16) __nv_bfloat16 Ws[S][BK * WST];

    const int tid = threadIdx.x;
    const int lane = tid & 31;
    const int wid = tid >> 5;
    const int wm = wid >> 1;
    const int wn = wid & 1;
    const int quad = lane >> 3;
    const int lq = lane & 7;
    const int g = lane >> 2;
    const int tg = lane & 3;
    const int row0 = blockIdx.x * BM;

    int a_soff[ACH]; const __nv_bfloat16* a_src[ACH]; int a_ok[ACH];
#pragma unroll
    for (int q = 0; q < ACH; q++) {
        int idx = tid + q * 256;
        int r = idx >> 2, c = (idx & 3) * 8;
        int gr = row0 + r;
        a_ok[q] = gr < n;
        a_src[q] = A + (size_t)gr * K + c;
        a_soff[q] = (r * AST + c) * 2;
    }
    int w_soff[WQN]; const __nv_bfloat16* w_src[WQN]; int w_ok[WQN];
#pragma unroll
    for (int q = 0; q < WQN; q++) {
        int idx = tid + q * 256;
        int k = idx / WCH, c8 = (idx % WCH) * 8;
        w_ok[q] = idx < BK * WCH;
        w_src[q] = Wm + (size_t)k * F + c8;
        w_soff[q] = (k * WST + c8) * 2;
    }

    float acc[2][NT][4];
#pragma unroll
    for (int i = 0; i < 2; i++)
#pragma unroll
        for (int j = 0; j < NT; j++)
#pragma unroll
            for (int q = 0; q < 4; q++) acc[i][j][q] = 0.0f;

    const int a_row = wm * 32 + (quad & 1) * 8 + lq;
    const int a_colq = (quad >> 1) * 8;
    const int b_rowq = (quad & 1) * 8 + lq;
    const int b_col = wn * WNW + (quad >> 1) * 8;

    const uint32_t as_base = smem_u32(As);
    const uint32_t ws_base = smem_u32(Ws);
    constexpr int ASZ = BM * AST * 2;
    constexpr int WSZ = BK * WST * 2;

    auto load_tile = [&](int kt, int s) {
        const uint32_t asb = as_base + s * ASZ;
        const uint32_t wsb = ws_base + s * WSZ;
        const int k0 = kt * BK;
#pragma unroll
        for (int q = 0; q < ACH; q++)
            cp16(asb + a_soff[q], a_src[q] + k0, a_ok[q]);
#pragma unroll
        for (int q = 0; q < WQN; q++)
            cp16(wsb + w_soff[q], w_src[q] + (size_t)k0 * F, w_ok[q]);
    };

#pragma unroll
    for (int s = 0; s < S - 1; s++) {
        if (s < KT) load_tile(s, s);
        cp_commit();
    }

    for (int kt = 0; kt < KT; kt++) {
        asm volatile("cp.async.wait_group %0;" :: "n"(S - 2));
        __syncthreads();
        {
            int nxt = kt + S - 1;
            if (nxt < KT) load_tile(nxt, nxt % S);
            cp_commit();
        }
        const int cur = kt % S;
        const uint32_t asb = as_base + cur * ASZ;
        const uint32_t wsb = ws_base + cur * WSZ;
#pragma unroll
        for (int kk = 0; kk < BK; kk += 16) {
            uint32_t af[2][4];
#pragma unroll
            for (int i = 0; i < 2; i++)
                ldsm_x4(af[i], asb + ((a_row + i * 16) * AST + kk + a_colq) * 2);

            uint32_t bfr[NT][2];
#pragma unroll
            for (int j2 = 0; j2 < NT / 2; j2++) {
                uint32_t r[4];
                ldsm_x4_t(r, wsb + ((kk + b_rowq) * WST + b_col + j2 * 16) * 2);
                bfr[2 * j2][0] = r[0]; bfr[2 * j2][1] = r[1];
                bfr[2 * j2 + 1][0] = r[2]; bfr[2 * j2 + 1][1] = r[3];
            }
#pragma unroll
            for (int j = 0; j < NT; j++)
#pragma unroll
                for (int i = 0; i < 2; i++) mma_bf16(acc[i][j], af[i], bfr[j][0], bfr[j][1]);
        }
    }

#pragma unroll
    for (int i = 0; i < 2; i++) {
        int gr0 = row0 + wm * 32 + i * 16 + g;
#pragma unroll
        for (int j = 0; j < NT; j++) {
            int col = wn * WNW + j * 8 + 2 * tg;
            if (gr0 < n)
                *(__nv_bfloat162*)(C + (size_t)gr0 * F + col) =
                    __floats2bfloat162_rn(acc[i][j][0], acc[i][j][1]);
            if (gr0 + 8 < n)
                *(__nv_bfloat162*)(C + (size_t)(gr0 + 8) * F + col) =
                    __floats2bfloat162_rn(acc[i][j][2], acc[i][j][3]);
        }
    }
}

// ============ fp32-input GEMM (layer 1): register-staged A, 2-slot bf16 As ring =======
// Each thread owns 16 fp32 A elems/tile (row tid/4, cols (tid%4)*8..+7 -> 4 float4).
template <int K, int F>
__global__ void __launch_bounds__(256) k_gemm_f32in(const float* __restrict__ A,
                                                    const __nv_bfloat16* __restrict__ Wm,
                                                    __nv_bfloat16* __restrict__ C, int n) {
    constexpr int BM = 128, BK = 32, S = 3;
    constexpr int AST = 40;
    constexpr int WST = F + 8;
    constexpr int WNW = F / 2;
    constexpr int NT = WNW / 8;
    constexpr int KT = K / BK;
    constexpr int WCH = F / 8;
    constexpr int WQN = (BK * WCH + 255) / 256;

    __shared__ __align__(16) __nv_bfloat16 As[2][BM * AST];
    __shared__ __align__(16) __nv_bfloat16 Ws[S][BK * WST];

    const int tid = threadIdx.x;
    const int lane = tid & 31;
    const int wid = tid >> 5;
    const int wm = wid >> 1;
    const int wn = wid & 1;
    const int quad = lane >> 3;
    const int lq = lane & 7;
    const int g = lane >> 2;
    const int tg = lane & 3;
    const int row0 = blockIdx.x * BM;

    // A register staging: 2 rows per thread (r and r+64? no) — each thread: 1 row, 16 cols.
    // 128 rows x 32 cols / 256 thr = 16 elems: row = tid/2, cols (tid&1)*16..+15.
    const int a_r = tid >> 1;
    const int a_c = (tid & 1) * 16;
    const int a_gr = row0 + a_r;
    const int a_ok = a_gr < n;
    const float* a_srcp = A + (size_t)a_gr * K + a_c;
    const int a_soff = (a_r * AST + a_c) * 2;

    int w_soff[WQN]; const __nv_bfloat16* w_src[WQN]; int w_ok[WQN];
#pragma unroll
    for (int q = 0; q < WQN; q++) {
        int idx = tid + q * 256;
        int k = idx / WCH, c8 = (idx % WCH) * 8;
        w_ok[q] = idx < BK * WCH;
        w_src[q] = Wm + (size_t)k * F + c8;
        w_soff[q] = (k * WST + c8) * 2;
    }

    float acc[2][NT][4];
#pragma unroll
    for (int i = 0; i < 2; i++)
#pragma unroll
        for (int j = 0; j < NT; j++)
#pragma unroll
            for (int q = 0; q < 4; q++) acc[i][j][q] = 0.0f;

    const int a_row = wm * 32 + (quad & 1) * 8 + lq;
    const int a_colq = (quad >> 1) * 8;
    const int b_rowq = (quad & 1) * 8 + lq;
    const int b_col = wn * WNW + (quad >> 1) * 8;

    const uint32_t as_base = smem_u32(As);
    const uint32_t ws_base = smem_u32(Ws);
    constexpr int ASZ = BM * AST * 2;
    constexpr int WSZ = BK * WST * 2;

    auto load_w = [&](int kt, int s) {
        const uint32_t wsb = ws_base + s * WSZ;
        const int k0 = kt * BK;
#pragma unroll
        for (int q = 0; q < WQN; q++)
            cp16(wsb + w_soff[q], w_src[q] + (size_t)k0 * F, w_ok[q]);
    };

    float4 ra[4];
    auto ldg_a = [&](int kt) {
        const float* p = a_srcp + kt * BK;
        if (a_ok) {
            ra[0] = *(const float4*)(p + 0);
            ra[1] = *(const float4*)(p + 4);
            ra[2] = *(const float4*)(p + 8);
            ra[3] = *(const float4*)(p + 12);
        }
    };
    auto sts_a = [&](int slot) {
        __nv_bfloat16* dst = As[slot] + a_r * AST + a_c;
        if (a_ok) {
            uint4 o;
            ((__nv_bfloat162*)&o)[0] = __floats2bfloat162_rn(ra[0].x, ra[0].y);
            ((__nv_bfloat162*)&o)[1] = __floats2bfloat162_rn(ra[0].z, ra[0].w);
            ((__nv_bfloat162*)&o)[2] = __floats2bfloat162_rn(ra[1].x, ra[1].y);
            ((__nv_bfloat162*)&o)[3] = __floats2bfloat162_rn(ra[1].z, ra[1].w);
            *(uint4*)dst = o;
            uint4 o2;
            ((__nv_bfloat162*)&o2)[0] = __floats2bfloat162_rn(ra[2].x, ra[2].y);
            ((__nv_bfloat162*)&o2)[1] = __floats2bfloat162_rn(ra[2].z, ra[2].w);
            ((__nv_bfloat162*)&o2)[2] = __floats2bfloat162_rn(ra[3].x, ra[3].y);
            ((__nv_bfloat162*)&o2)[3] = __floats2bfloat162_rn(ra[3].z, ra[3].w);
            *(uint4*)(dst + 8) = o2;
        } else {
            uint4 z = make_uint4(0, 0, 0, 0);
            *(uint4*)(As[slot] + a_r * AST + a_c) = z;
            *(uint4*)(As[slot] + a_r * AST + a_c + 8) = z;
        }
    };

    // prologue
    ldg_a(0);
#pragma unroll
    for (int s = 0; s < S - 1; s++) {
        if (s < KT) load_w(s, s);
        cp_commit();
    }

    for (int kt = 0; kt < KT; kt++) {
        const int cur = kt & 1;
        sts_a(cur);                       // convert this tile's regs -> smem
        asm volatile("cp.async.wait_group %0;" :: "n"(S - 2));
        __syncthreads();
        ldg_a(kt + 1 < KT ? kt + 1 : kt); // prefetch next tile's A into regs
        {
            int nxt = kt + S - 1;
            if (nxt < KT) load_w(nxt, nxt % S);
            cp_commit();
        }
        const uint32_t asb = as_base + cur * ASZ;
        const uint32_t wsb = ws_base + (kt % S) * WSZ;
#pragma unroll
        for (int kk = 0; kk < BK; kk += 16) {
            uint32_t af[2][4];
#pragma unroll
            for (int i = 0; i < 2; i++)
                ldsm_x4(af[i], asb + ((a_row + i * 16) * AST + kk + a_colq) * 2);

            uint32_t bfr[NT][2];
#pragma unroll
            for (int j2 = 0; j2 < NT / 2; j2++) {
                uint32_t r[4];
                ldsm_x4_t(r, wsb + ((kk + b_rowq) * WST + b_col + j2 * 16) * 2);
                bfr[2 * j2][0] = r[0]; bfr[2 * j2][1] = r[1];
                bfr[2 * j2 + 1][0] = r[2]; bfr[2 * j2 + 1][1] = r[3];
            }
#pragma unroll
            for (int j = 0; j < NT; j++)
#pragma unroll
                for (int i = 0; i < 2; i++) mma_bf16(acc[i][j], af[i], bfr[j][0], bfr[j][1]);
        }
    }

#pragma unroll
    for (int i = 0; i < 2; i++) {
        int gr0 = row0 + wm * 32 + i * 16 + g;
#pragma unroll
        for (int j = 0; j < NT; j++) {
            int col = wn * WNW + j * 8 + 2 * tg;
            if (gr0 < n)
                *(__nv_bfloat162*)(C + (size_t)gr0 * F + col) =
                    __floats2bfloat162_rn(acc[i][j][0], acc[i][j][1]);
            if (gr0 + 8 < n)
                *(__nv_bfloat162*)(C + (size_t)(gr0 + 8) * F + col) =
                    __floats2bfloat162_rn(acc[i][j][2], acc[i][j][3]);
        }
    }
}

// ---------------- aggregation: 4-edge pipeline, bf16 gather, fp32 accum ----------------
__device__ __forceinline__ void fma_bf16x4(float4& acc, uint2 v, float nm) {
    float2 lo = __bfloat1622float2(*(const __nv_bfloat162*)&v.x);
    float2 hi = __bfloat1622float2(*(const __nv_bfloat162*)&v.y);
    acc.x = fmaf(lo.x, nm, acc.x);
    acc.y = fmaf(lo.y, nm, acc.y);
    acc.z = fmaf(hi.x, nm, acc.z);
    acc.w = fmaf(hi.y, nm, acc.w);
}

__global__ void k_agg128(const __nv_bfloat16* __restrict__ h, const float* __restrict__ b,
                         __nv_bfloat16* __restrict__ out, int n) {
    int gw = (blockIdx.x * blockDim.x + threadIdx.x) >> 5;
    int lane = threadIdx.x & 31;
    if (gw >= n) return;

    float4 acc = make_float4(0.f, 0.f, 0.f, 0.f);
    const int beg = g_offs[gw];
    const int end = g_offs[gw + 1];

    int e = beg;
    if ((e & 1) && e < end) {
        int2 e0 = g_edge[e];
        uint2 v0 = *(const uint2*)(h + (size_t)e0.x * 128 + lane * 4);
        fma_bf16x4(acc, v0, __int_as_float(e0.y));
        e++;
    }
    for (; e + 3 < end; e += 4) {
        int4 p0 = *(const int4*)&g_edge[e];
        int4 p1 = *(const int4*)&g_edge[e + 2];
        uint2 v0 = *(const uint2*)(h + (size_t)p0.x * 128 + lane * 4);
        uint2 v1 = *(const uint2*)(h + (size_t)p0.z * 128 + lane * 4);
        uint2 v2 = *(const uint2*)(h + (size_t)p1.x * 128 + lane * 4);
        uint2 v3 = *(const uint2*)(h + (size_t)p1.z * 128 + lane * 4);
        fma_bf16x4(acc, v0, __int_as_float(p0.y));
        fma_bf16x4(acc, v1, __int_as_float(p0.w));
        fma_bf16x4(acc, v2, __int_as_float(p1.y));
        fma_bf16x4(acc, v3, __int_as_float(p1.w));
    }
    for (; e + 1 < end; e += 2) {
        int4 p0 = *(const int4*)&g_edge[e];
        uint2 v0 = *(const uint2*)(h + (size_t)p0.x * 128 + lane * 4);
        uint2 v1 = *(const uint2*)(h + (size_t)p0.z * 128 + lane * 4);
        fma_bf16x4(acc, v0, __int_as_float(p0.y));
        fma_bf16x4(acc, v1, __int_as_float(p0.w));
    }
    if (e < end) {
        int2 e0 = g_edge[e];
        uint2 v0 = *(const uint2*)(h + (size_t)e0.x * 128 + lane * 4);
        fma_bf16x4(acc, v0, __int_as_float(e0.y));
    }
    {
        float di = g_dinv[gw];
        uint2 v = *(const uint2*)(h + (size_t)gw * 128 + lane * 4);
        fma_bf16x4(acc, v, di * di);
    }
    float4 bv = *(const float4*)(b + lane * 4);
    acc.x = fmaxf(acc.x + bv.x, 0.f);
    acc.y = fmaxf(acc.y + bv.y, 0.f);
    acc.z = fmaxf(acc.z + bv.z, 0.f);
    acc.w = fmaxf(acc.w + bv.w, 0.f);
    uint2 o;
    *(__nv_bfloat162*)&o.x = __floats2bfloat162_rn(acc.x, acc.y);
    *(__nv_bfloat162*)&o.y = __floats2bfloat162_rn(acc.z, acc.w);
    *(uint2*)(out + (size_t)gw * 128 + lane * 4) = o;
}

__global__ void k_agg64_lsm(const __nv_bfloat16* __restrict__ h, const float* __restrict__ b,
                            float* __restrict__ out, int n) {
    int gw = (blockIdx.x * blockDim.x + threadIdx.x) >> 5;
    int lane = threadIdx.x & 31;
    if (gw >= n) return;

    float2 acc = make_float2(0.f, 0.f);
    const int beg = g_offs[gw];
    const int end = g_offs[gw + 1];

    auto gfma = [&](int s, float nm) {
        uint32_t v = *(const uint32_t*)(h + (size_t)s * 64 + lane * 2);
        float2 f = __bfloat1622float2(*(const __nv_bfloat162*)&v);
        acc.x = fmaf(f.x, nm, acc.x);
        acc.y = fmaf(f.y, nm, acc.y);
    };

    int e = beg;
    if ((e & 1) && e < end) {
        int2 e0 = g_edge[e];
        gfma(e0.x, __int_as_float(e0.y));
        e++;
    }
    for (; e + 3 < end; e += 4) {
        int4 p0 = *(const int4*)&g_edge[e];
        int4 p1 = *(const int4*)&g_edge[e + 2];
        gfma(p0.x, __int_as_float(p0.y));
        gfma(p0.z, __int_as_float(p0.w));
        gfma(p1.x, __int_as_float(p1.y));
        gfma(p1.z, __int_as_float(p1.w));
    }
    for (; e + 1 < end; e += 2) {
        int4 p0 = *(const int4*)&g_edge[e];
        gfma(p0.x, __int_as_float(p0.y));
        gfma(p0.z, __int_as_float(p0.w));
    }
    if (e < end) {
        int2 e0 = g_edge[e];
        gfma(e0.x, __int_as_float(e0.y));
    }
    {
        float di = g_dinv[gw];
        gfma(gw, di * di);
    }
    float2 bv = *(const float2*)(b + lane * 2);
    acc.x += bv.x;
    acc.y += bv.y;

    float m = fmaxf(acc.x, acc.y);
#pragma unroll
    for (int o = 16; o > 0; o >>= 1) m = fmaxf(m, __shfl_xor_sync(0xFFFFFFFFu, m, o));
    float se = expf(acc.x - m) + expf(acc.y - m);
#pragma unroll
    for (int o = 16; o > 0; o >>= 1) se += __shfl_xor_sync(0xFFFFFFFFu, se, o);
    float ls = m + logf(se);
    *(float2*)(out + (size_t)gw * 64 + lane * 2) = make_float2(acc.x - ls, acc.y - ls);
}

// ---------------- launch ----------------
extern "C" void kernel_launch(void* const* d_in, const int* in_sizes, int n_in,
                              void* d_out, int out_size) {
    const float* x  = (const float*)d_in[0];
    const int* ei   = (const int*)d_in[1];
    const float* W0 = (const float*)d_in[2];
    const float* b0 = (const float*)d_in[3];
    const float* W1 = (const float*)d_in[4];
    const float* b1 = (const float*)d_in[5];
    const float* W2 = (const float*)d_in[6];
    const float* b2 = (const float*)d_in[7];
    float* out = (float*)d_out;

    const int N = in_sizes[0] / DIN;
    const int E = in_sizes[1] / 2;
    const int* src = ei;
    const int* dst = ei + E;

    __nv_bfloat16 *h_ptr = nullptr, *a_ptr = nullptr;
    __nv_bfloat16 *w0_ptr = nullptr, *w1_ptr = nullptr, *w2_ptr = nullptr;
    int* deg_ptr = nullptr;
    void* st_ptr = nullptr;
    cudaGetSymbolAddress((void**)&h_ptr, g_h);
    cudaGetSymbolAddress((void**)&a_ptr, g_a);
    cudaGetSymbolAddress((void**)&w0_ptr, g_w0);
    cudaGetSymbolAddress((void**)&w1_ptr, g_w1);
    cudaGetSymbolAddress((void**)&w2_ptr, g_w2);
    cudaGetSymbolAddress((void**)&deg_ptr, g_deg);
    cudaGetSymbolAddress(&st_ptr, g_state);

    const int TB = 256;
    const int nb = (N + 4095) / 4096;
    const int e4 = (E + 3) / 4;

    // ---- fork: CSR build on side stream ----
    cudaEventRecord(g_sx.ev0, 0);
    cudaStreamWaitEvent(g_sx.s2, g_sx.ev0, 0);
    cudaMemsetAsync(deg_ptr, 0, (size_t)N * sizeof(int), g_sx.s2);
    cudaMemsetAsync(st_ptr, 0, 64 * sizeof(unsigned long long), g_sx.s2);
    k_count<<<(e4 + TB - 1) / TB, TB, 0, g_sx.s2>>>(dst, E);
    k_scan_all<<<nb, 512, 0, g_sx.s2>>>(N, nb);
    k_fill<<<(e4 + TB - 1) / TB, TB, 0, g_sx.s2>>>(src, dst, E);
    cudaEventRecord(g_sx.ev1, g_sx.s2);

    // ---- main stream: weight convert + GEMM1 (fp32 A staged in registers) ----
    {
        int wch = (DIN * DH + DH * DH + DH * DOUT) / 8;
        k_cvt_w<<<(wch + TB - 1) / TB, TB>>>(W0, W1, W2);
    }

    const int gemm_grid = (N + 127) / 128;
    const int agg_grid = (N * 32 + TB - 1) / TB;

    k_gemm_f32in<DIN, DH><<<gemm_grid, 256>>>(x, w0_ptr, h_ptr, N);

    // ---- join: agg needs CSR ----
    cudaStreamWaitEvent(0, g_sx.ev1, 0);

    k_agg128<<<agg_grid, TB>>>(h_ptr, b0, a_ptr, N);

    k_gemm_bf16<DH, DH><<<gemm_grid, 256>>>(a_ptr, w1_ptr, h_ptr, N);
    k_agg128<<<agg_grid, TB>>>(h_ptr, b1, a_ptr, N);

    k_gemm_bf16<DH, DOUT><<<gemm_grid, 256>>>(a_ptr, w2_ptr, h_ptr, N);
    k_agg64_lsm<<<agg_grid, TB>>>(h_ptr, b2, out, N);
}

// round 10
// speedup vs baseline: 1.0839x; 1.0839x over previous
#include <cuda_runtime.h>
#include <cuda_bf16.h>
#include <math.h>
#include <stdint.h>

#define N_NODES 50000
#define E_EDGES 800000
#define DIN 256
#define DH 128
#define DOUT 64

// ---------------- scratch (static device globals; no allocation) ----------------
__device__ __nv_bfloat16 g_xb[(size_t)N_NODES * DIN];
__device__ __nv_bfloat16 g_h[(size_t)N_NODES * DH];
__device__ __nv_bfloat16 g_a[(size_t)N_NODES * DH];
__device__ __nv_bfloat16 g_w0[DIN * DH];
__device__ __nv_bfloat16 g_w1[DH * DH];
__device__ __nv_bfloat16 g_w2[DH * DOUT];
__device__ float g_dinv[N_NODES];
__device__ int   g_deg[N_NODES];
__device__ int   g_offs[N_NODES + 1];
__device__ int   g_cursor[N_NODES];
__device__ int2  g_edge[E_EDGES];
__device__ unsigned long long g_state[64];

// ---------------- host-side stream/event singletons ----------------
struct HxStreams {
    cudaStream_t s2;
    cudaEvent_t ev0, ev1;
    HxStreams() {
        cudaStreamCreateWithFlags(&s2, cudaStreamNonBlocking);
        cudaEventCreateWithFlags(&ev0, cudaEventDisableTiming);
        cudaEventCreateWithFlags(&ev1, cudaEventDisableTiming);
    }
};
static HxStreams g_sx;

// ---------------- conversion: x + all weights in ONE launch ----------------
// chunks are 8 floats. x chunks: [0, NX8). weight chunks follow.
__global__ void k_cvt_all(const float* __restrict__ x,
                          const float* __restrict__ W0, const float* __restrict__ W1,
                          const float* __restrict__ W2, int nx8) {
    int i = blockIdx.x * blockDim.x + threadIdx.x;
    const int c0 = DIN * DH / 8, c1 = DH * DH / 8, c2 = DH * DOUT / 8;
    const float* s; __nv_bfloat16* d; int off;
    if (i < nx8) { s = x; d = g_xb; off = i; }
    else {
        int j = i - nx8;
        if (j < c0) { s = W0; d = g_w0; off = j; }
        else if (j < c0 + c1) { s = W1; d = g_w1; off = j - c0; }
        else if (j < c0 + c1 + c2) { s = W2; d = g_w2; off = j - c0 - c1; }
        else return;
    }
    const float4* p = (const float4*)(s + (size_t)off * 8);
    float4 v0 = p[0], v1 = p[1];
    __nv_bfloat16 t[8];
    t[0] = __float2bfloat16(v0.x); t[1] = __float2bfloat16(v0.y);
    t[2] = __float2bfloat16(v0.z); t[3] = __float2bfloat16(v0.w);
    t[4] = __float2bfloat16(v1.x); t[5] = __float2bfloat16(v1.y);
    t[6] = __float2bfloat16(v1.z); t[7] = __float2bfloat16(v1.w);
    *(uint4*)(d + (size_t)off * 8) = *(uint4*)t;
}

// ---------------- CSR construction (R7 scalar versions) ----------------
__global__ void k_count(const int* __restrict__ dst, int E) {
    int i = blockIdx.x * blockDim.x + threadIdx.x;
    if (i < E) atomicAdd(&g_deg[dst[i]], 1);
}

// 512 threads x 8 elems = 4096/block -> 13 blocks; single-round lookback.
__global__ void k_scan_all(int n, int nb) {
    __shared__ int wsum[16];
    __shared__ int s_base;
    const int t = threadIdx.x;
    const int lane = t & 31, w = t >> 5;
    const int base = blockIdx.x * 4096 + t * 8;

    int d[8];
    if (base + 7 < n) {
        int4 a = *(const int4*)(g_deg + base);
        int4 b = *(const int4*)(g_deg + base + 4);
        d[0] = a.x; d[1] = a.y; d[2] = a.z; d[3] = a.w;
        d[4] = b.x; d[5] = b.y; d[6] = b.z; d[7] = b.w;
    } else {
#pragma unroll
        for (int j = 0; j < 8; j++) d[j] = (base + j < n) ? g_deg[base + j] : 0;
    }
    if (base + 7 < n) {
        float4 f0 = make_float4(rsqrtf((float)d[0] + 1.f), rsqrtf((float)d[1] + 1.f),
                                rsqrtf((float)d[2] + 1.f), rsqrtf((float)d[3] + 1.f));
        float4 f1 = make_float4(rsqrtf((float)d[4] + 1.f), rsqrtf((float)d[5] + 1.f),
                                rsqrtf((float)d[6] + 1.f), rsqrtf((float)d[7] + 1.f));
        *(float4*)(g_dinv + base) = f0;
        *(float4*)(g_dinv + base + 4) = f1;
    } else {
#pragma unroll
        for (int j = 0; j < 8; j++)
            if (base + j < n) g_dinv[base + j] = rsqrtf((float)d[j] + 1.f);
    }

    int pre[8];
    int run = 0;
#pragma unroll
    for (int j = 0; j < 8; j++) { pre[j] = run; run += d[j]; }

    int ws = run;
#pragma unroll
    for (int off = 1; off < 32; off <<= 1) {
        int v = __shfl_up_sync(0xFFFFFFFFu, ws, off);
        if (lane >= off) ws += v;
    }
    if (lane == 31) wsum[w] = ws;
    __syncthreads();
    if (w == 0 && lane < 16) {
        int v = wsum[lane];
#pragma unroll
        for (int off = 1; off < 16; off <<= 1) {
            int u = __shfl_up_sync(0x0000FFFFu, v, off);
            if (lane >= off) v += u;
        }
        wsum[lane] = v;
    }
    __syncthreads();

    if (t == 0) {
        unsigned long long pkt = (((unsigned long long)(unsigned)wsum[15]) << 2) | 1ull;
        atomicExch(&g_state[blockIdx.x], pkt);
    }
    if (w == 0) {
        int sum = 0;
        volatile unsigned long long* st = (volatile unsigned long long*)g_state;
        for (int p0 = (int)blockIdx.x - 1; p0 >= 0; p0 -= 32) {
            int idx = p0 - lane;
            if (idx >= 0) {
                unsigned long long v;
                do { v = st[idx]; } while ((v & 3ull) == 0ull);
                sum += (int)(v >> 2);
            }
        }
#pragma unroll
        for (int off = 16; off > 0; off >>= 1)
            sum += __shfl_xor_sync(0xFFFFFFFFu, sum, off);
        if (lane == 0) s_base = sum;
    }
    __syncthreads();

    const int blk = s_base;
    int wbase = (w == 0) ? 0 : wsum[w - 1];
    int tbase = blk + wbase + ws - run;
    if (base + 7 < n) {
        int4 o0 = make_int4(tbase + pre[0], tbase + pre[1], tbase + pre[2], tbase + pre[3]);
        int4 o1 = make_int4(tbase + pre[4], tbase + pre[5], tbase + pre[6], tbase + pre[7]);
        *(int4*)(g_offs + base) = o0;   *(int4*)(g_offs + base + 4) = o1;
        *(int4*)(g_cursor + base) = o0; *(int4*)(g_cursor + base + 4) = o1;
    } else {
#pragma unroll
        for (int j = 0; j < 8; j++)
            if (base + j < n) { g_offs[base + j] = tbase + pre[j]; g_cursor[base + j] = tbase + pre[j]; }
    }
    if (blockIdx.x == (unsigned)(nb - 1) && t == 511) g_offs[n] = blk + wsum[15];
}

__global__ void k_fill(const int* __restrict__ src, const int* __restrict__ dst, int E) {
    int i = blockIdx.x * blockDim.x + threadIdx.x;
    if (i < E) {
        int d = dst[i];
        int s = src[i];
        int pos = atomicAdd(&g_cursor[d], 1);
        g_edge[pos] = make_int2(s, __float_as_int(g_dinv[s] * g_dinv[d]));
    }
}

// ---------------- bf16 GEMM: 3-stage cp.async, BM=128, ldmatrix + mma (R7-exact) -----
__device__ __forceinline__ uint32_t smem_u32(const void* p) {
    return (uint32_t)__cvta_generic_to_shared(p);
}
__device__ __forceinline__ void cp16(uint32_t dst, const void* src, int pred) {
    asm volatile("cp.async.cg.shared.global [%0], [%1], 16, %2;"
                 :: "r"(dst), "l"(src), "r"(pred ? 16 : 0));
}
__device__ __forceinline__ void cp_commit() {
    asm volatile("cp.async.commit_group;");
}
__device__ __forceinline__ void ldsm_x4(uint32_t r[4], uint32_t addr) {
    asm volatile("ldmatrix.sync.aligned.m8n8.x4.shared.b16 {%0,%1,%2,%3}, [%4];"
                 : "=r"(r[0]), "=r"(r[1]), "=r"(r[2]), "=r"(r[3]) : "r"(addr));
}
__device__ __forceinline__ void ldsm_x4_t(uint32_t r[4], uint32_t addr) {
    asm volatile("ldmatrix.sync.aligned.m8n8.x4.trans.shared.b16 {%0,%1,%2,%3}, [%4];"
                 : "=r"(r[0]), "=r"(r[1]), "=r"(r[2]), "=r"(r[3]) : "r"(addr));
}
__device__ __forceinline__ void mma_bf16(float c[4], const uint32_t a[4],
                                         uint32_t b0, uint32_t b1) {
    asm volatile(
        "mma.sync.aligned.m16n8k16.row.col.f32.bf16.bf16.f32 "
        "{%0,%1,%2,%3},{%4,%5,%6,%7},{%8,%9},{%0,%1,%2,%3};"
        : "+f"(c[0]), "+f"(c[1]), "+f"(c[2]), "+f"(c[3])
        : "r"(a[0]), "r"(a[1]), "r"(a[2]), "r"(a[3]), "r"(b0), "r"(b1));
}

template <int K, int F>
__global__ void __launch_bounds__(256) k_gemm_bf16(const __nv_bfloat16* __restrict__ A,
                                                   const __nv_bfloat16* __restrict__ Wm,
                                                   __nv_bfloat16* __restrict__ C, int n) {
    constexpr int BM = 128, BK = 32, S = 3;
    constexpr int AST = 40;
    constexpr int WST = F + 8;
    constexpr int WNW = F / 2;
    constexpr int NT = WNW / 8;
    constexpr int KT = K / BK;
    constexpr int WCH = F / 8;
    constexpr int ACH = 2;
    constexpr int WQN = (BK * WCH + 255) / 256;

    __shared__ __align__(16) __nv_bfloat16 As[S][BM * AST];
    __shared__ __align__(16) __nv_bfloat16 Ws[S][BK * WST];

    const int tid = threadIdx.x;
    const int lane = tid & 31;
    const int wid = tid >> 5;
    const int wm = wid >> 1;
    const int wn = wid & 1;
    const int quad = lane >> 3;
    const int lq = lane & 7;
    const int g = lane >> 2;
    const int tg = lane & 3;
    const int row0 = blockIdx.x * BM;

    int a_soff[ACH]; const __nv_bfloat16* a_src[ACH]; int a_ok[ACH];
#pragma unroll
    for (int q = 0; q < ACH; q++) {
        int idx = tid + q * 256;
        int r = idx >> 2, c = (idx & 3) * 8;
        int gr = row0 + r;
        a_ok[q] = gr < n;
        a_src[q] = A + (size_t)gr * K + c;
        a_soff[q] = (r * AST + c) * 2;
    }
    int w_soff[WQN]; const __nv_bfloat16* w_src[WQN]; int w_ok[WQN];
#pragma unroll
    for (int q = 0; q < WQN; q++) {
        int idx = tid + q * 256;
        int k = idx / WCH, c8 = (idx % WCH) * 8;
        w_ok[q] = idx < BK * WCH;
        w_src[q] = Wm + (size_t)k * F + c8;
        w_soff[q] = (k * WST + c8) * 2;
    }

    float acc[2][NT][4];
#pragma unroll
    for (int i = 0; i < 2; i++)
#pragma unroll
        for (int j = 0; j < NT; j++)
#pragma unroll
            for (int q = 0; q < 4; q++) acc[i][j][q] = 0.0f;

    const int a_row = wm * 32 + (quad & 1) * 8 + lq;
    const int a_colq = (quad >> 1) * 8;
    const int b_rowq = (quad & 1) * 8 + lq;
    const int b_col = wn * WNW + (quad >> 1) * 8;

    const uint32_t as_base = smem_u32(As);
    const uint32_t ws_base = smem_u32(Ws);
    constexpr int ASZ = BM * AST * 2;
    constexpr int WSZ = BK * WST * 2;

    auto load_tile = [&](int kt, int s) {
        const uint32_t asb = as_base + s * ASZ;
        const uint32_t wsb = ws_base + s * WSZ;
        const int k0 = kt * BK;
#pragma unroll
        for (int q = 0; q < ACH; q++)
            cp16(asb + a_soff[q], a_src[q] + k0, a_ok[q]);
#pragma unroll
        for (int q = 0; q < WQN; q++)
            cp16(wsb + w_soff[q], w_src[q] + (size_t)k0 * F, w_ok[q]);
    };

#pragma unroll
    for (int s = 0; s < S - 1; s++) {
        if (s < KT) load_tile(s, s);
        cp_commit();
    }

    for (int kt = 0; kt < KT; kt++) {
        asm volatile("cp.async.wait_group %0;" :: "n"(S - 2));
        __syncthreads();
        {
            int nxt = kt + S - 1;
            if (nxt < KT) load_tile(nxt, nxt % S);
            cp_commit();
        }
        const int cur = kt % S;
        const uint32_t asb = as_base + cur * ASZ;
        const uint32_t wsb = ws_base + cur * WSZ;
#pragma unroll
        for (int kk = 0; kk < BK; kk += 16) {
            uint32_t af[2][4];
#pragma unroll
            for (int i = 0; i < 2; i++)
                ldsm_x4(af[i], asb + ((a_row + i * 16) * AST + kk + a_colq) * 2);

            uint32_t bfr[NT][2];
#pragma unroll
            for (int j2 = 0; j2 < NT / 2; j2++) {
                uint32_t r[4];
                ldsm_x4_t(r, wsb + ((kk + b_rowq) * WST + b_col + j2 * 16) * 2);
                bfr[2 * j2][0] = r[0]; bfr[2 * j2][1] = r[1];
                bfr[2 * j2 + 1][0] = r[2]; bfr[2 * j2 + 1][1] = r[3];
            }
#pragma unroll
            for (int j = 0; j < NT; j++)
#pragma unroll
                for (int i = 0; i < 2; i++) mma_bf16(acc[i][j], af[i], bfr[j][0], bfr[j][1]);
        }
    }

#pragma unroll
    for (int i = 0; i < 2; i++) {
        int gr0 = row0 + wm * 32 + i * 16 + g;
#pragma unroll
        for (int j = 0; j < NT; j++) {
            int col = wn * WNW + j * 8 + 2 * tg;
            if (gr0 < n)
                *(__nv_bfloat162*)(C + (size_t)gr0 * F + col) =
                    __floats2bfloat162_rn(acc[i][j][0], acc[i][j][1]);
            if (gr0 + 8 < n)
                *(__nv_bfloat162*)(C + (size_t)(gr0 + 8) * F + col) =
                    __floats2bfloat162_rn(acc[i][j][2], acc[i][j][3]);
        }
    }
}

// ---------------- aggregation (R7-exact 2-edge pipeline) ----------------
__device__ __forceinline__ void fma_bf16x4(float4& acc, uint2 v, float nm) {
    float2 lo = __bfloat1622float2(*(const __nv_bfloat162*)&v.x);
    float2 hi = __bfloat1622float2(*(const __nv_bfloat162*)&v.y);
    acc.x = fmaf(lo.x, nm, acc.x);
    acc.y = fmaf(lo.y, nm, acc.y);
    acc.z = fmaf(hi.x, nm, acc.z);
    acc.w = fmaf(hi.y, nm, acc.w);
}

__global__ void k_agg128(const __nv_bfloat16* __restrict__ h, const float* __restrict__ b,
                         __nv_bfloat16* __restrict__ out, int n) {
    int gw = (blockIdx.x * blockDim.x + threadIdx.x) >> 5;
    int lane = threadIdx.x & 31;
    if (gw >= n) return;

    float4 acc = make_float4(0.f, 0.f, 0.f, 0.f);
    const int beg = g_offs[gw];
    const int end = g_offs[gw + 1];

    int e = beg;
    for (; e + 1 < end; e += 2) {
        int2 e0 = g_edge[e];
        int2 e1 = g_edge[e + 1];
        uint2 v0 = *(const uint2*)(h + (size_t)e0.x * 128 + lane * 4);
        uint2 v1 = *(const uint2*)(h + (size_t)e1.x * 128 + lane * 4);
        fma_bf16x4(acc, v0, __int_as_float(e0.y));
        fma_bf16x4(acc, v1, __int_as_float(e1.y));
    }
    if (e < end) {
        int2 e0 = g_edge[e];
        uint2 v0 = *(const uint2*)(h + (size_t)e0.x * 128 + lane * 4);
        fma_bf16x4(acc, v0, __int_as_float(e0.y));
    }
    {
        float di = g_dinv[gw];
        uint2 v = *(const uint2*)(h + (size_t)gw * 128 + lane * 4);
        fma_bf16x4(acc, v, di * di);
    }
    float4 bv = *(const float4*)(b + lane * 4);
    acc.x = fmaxf(acc.x + bv.x, 0.f);
    acc.y = fmaxf(acc.y + bv.y, 0.f);
    acc.z = fmaxf(acc.z + bv.z, 0.f);
    acc.w = fmaxf(acc.w + bv.w, 0.f);
    uint2 o;
    *(__nv_bfloat162*)&o.x = __floats2bfloat162_rn(acc.x, acc.y);
    *(__nv_bfloat162*)&o.y = __floats2bfloat162_rn(acc.z, acc.w);
    *(uint2*)(out + (size_t)gw * 128 + lane * 4) = o;
}

__global__ void k_agg64_lsm(const __nv_bfloat16* __restrict__ h, const float* __restrict__ b,
                            float* __restrict__ out, int n) {
    int gw = (blockIdx.x * blockDim.x + threadIdx.x) >> 5;
    int lane = threadIdx.x & 31;
    if (gw >= n) return;

    float2 acc = make_float2(0.f, 0.f);
    const int beg = g_offs[gw];
    const int end = g_offs[gw + 1];

    int e = beg;
    for (; e + 1 < end; e += 2) {
        int2 e0 = g_edge[e];
        int2 e1 = g_edge[e + 1];
        uint32_t v0 = *(const uint32_t*)(h + (size_t)e0.x * 64 + lane * 2);
        uint32_t v1 = *(const uint32_t*)(h + (size_t)e1.x * 64 + lane * 2);
        float2 f0 = __bfloat1622float2(*(const __nv_bfloat162*)&v0);
        float2 f1 = __bfloat1622float2(*(const __nv_bfloat162*)&v1);
        float n0 = __int_as_float(e0.y), n1 = __int_as_float(e1.y);
        acc.x = fmaf(f0.x, n0, acc.x); acc.y = fmaf(f0.y, n0, acc.y);
        acc.x = fmaf(f1.x, n1, acc.x); acc.y = fmaf(f1.y, n1, acc.y);
    }
    if (e < end) {
        int2 e0 = g_edge[e];
        uint32_t v0 = *(const uint32_t*)(h + (size_t)e0.x * 64 + lane * 2);
        float2 f0 = __bfloat1622float2(*(const __nv_bfloat162*)&v0);
        float n0 = __int_as_float(e0.y);
        acc.x = fmaf(f0.x, n0, acc.x); acc.y = fmaf(f0.y, n0, acc.y);
    }
    {
        float di = g_dinv[gw];
        float sw = di * di;
        uint32_t v = *(const uint32_t*)(h + (size_t)gw * 64 + lane * 2);
        float2 f = __bfloat1622float2(*(const __nv_bfloat162*)&v);
        acc.x = fmaf(f.x, sw, acc.x); acc.y = fmaf(f.y, sw, acc.y);
    }
    float2 bv = *(const float2*)(b + lane * 2);
    acc.x += bv.x;
    acc.y += bv.y;

    float m = fmaxf(acc.x, acc.y);
#pragma unroll
    for (int o = 16; o > 0; o >>= 1) m = fmaxf(m, __shfl_xor_sync(0xFFFFFFFFu, m, o));
    float se = expf(acc.x - m) + expf(acc.y - m);
#pragma unroll
    for (int o = 16; o > 0; o >>= 1) se += __shfl_xor_sync(0xFFFFFFFFu, se, o);
    float ls = m + logf(se);
    *(float2*)(out + (size_t)gw * 64 + lane * 2) = make_float2(acc.x - ls, acc.y - ls);
}

// ---------------- launch ----------------
extern "C" void kernel_launch(void* const* d_in, const int* in_sizes, int n_in,
                              void* d_out, int out_size) {
    const float* x  = (const float*)d_in[0];
    const int* ei   = (const int*)d_in[1];
    const float* W0 = (const float*)d_in[2];
    const float* b0 = (const float*)d_in[3];
    const float* W1 = (const float*)d_in[4];
    const float* b1 = (const float*)d_in[5];
    const float* W2 = (const float*)d_in[6];
    const float* b2 = (const float*)d_in[7];
    float* out = (float*)d_out;

    const int N = in_sizes[0] / DIN;
    const int E = in_sizes[1] / 2;
    const int* src = ei;
    const int* dst = ei + E;

    __nv_bfloat16 *xb_ptr = nullptr, *h_ptr = nullptr, *a_ptr = nullptr;
    __nv_bfloat16 *w0_ptr = nullptr, *w1_ptr = nullptr, *w2_ptr = nullptr;
    int* deg_ptr = nullptr;
    void* st_ptr = nullptr;
    cudaGetSymbolAddress((void**)&xb_ptr, g_xb);
    cudaGetSymbolAddress((void**)&h_ptr, g_h);
    cudaGetSymbolAddress((void**)&a_ptr, g_a);
    cudaGetSymbolAddress((void**)&w0_ptr, g_w0);
    cudaGetSymbolAddress((void**)&w1_ptr, g_w1);
    cudaGetSymbolAddress((void**)&w2_ptr, g_w2);
    cudaGetSymbolAddress((void**)&deg_ptr, g_deg);
    cudaGetSymbolAddress(&st_ptr, g_state);

    const int TB = 256;
    const int nb = (N + 4095) / 4096;

    // ---- fork: CSR build on side stream ----
    cudaEventRecord(g_sx.ev0, 0);
    cudaStreamWaitEvent(g_sx.s2, g_sx.ev0, 0);
    cudaMemsetAsync(deg_ptr, 0, (size_t)N * sizeof(int), g_sx.s2);
    cudaMemsetAsync(st_ptr, 0, 64 * sizeof(unsigned long long), g_sx.s2);
    k_count<<<(E + TB - 1) / TB, TB, 0, g_sx.s2>>>(dst, E);
    k_scan_all<<<nb, 512, 0, g_sx.s2>>>(N, nb);
    k_fill<<<(E + TB - 1) / TB, TB, 0, g_sx.s2>>>(src, dst, E);
    cudaEventRecord(g_sx.ev1, g_sx.s2);

    // ---- main stream: single convert (x + weights) + GEMM1 ----
    {
        int nx8 = N * DIN / 8;
        int total = nx8 + (DIN * DH + DH * DH + DH * DOUT) / 8;
        k_cvt_all<<<(total + TB - 1) / TB, TB>>>(x, W0, W1, W2, nx8);
    }

    const int gemm_grid = (N + 127) / 128;
    const int agg_grid = (N * 32 + TB - 1) / TB;

    k_gemm_bf16<DIN, DH><<<gemm_grid, 256>>>(xb_ptr, w0_ptr, h_ptr, N);

    // ---- join: agg needs CSR ----
    cudaStreamWaitEvent(0, g_sx.ev1, 0);

    k_agg128<<<agg_grid, TB>>>(h_ptr, b0, a_ptr, N);

    k_gemm_bf16<DH, DH><<<gemm_grid, 256>>>(a_ptr, w1_ptr, h_ptr, N);
    k_agg128<<<agg_grid, TB>>>(h_ptr, b1, a_ptr, N);

    k_gemm_bf16<DH, DOUT><<<gemm_grid, 256>>>(a_ptr, w2_ptr, h_ptr, N);
    k_agg64_lsm<<<agg_grid, TB>>>(h_ptr, b2, out, N);
}